// round 7
// baseline (speedup 1.0000x reference)
#include <cuda_runtime.h>
#include <cstdint>

#define N_NODES 50000
#define N_EDGES 800000
#define N_E2    850000      // edges + self loops
#define IN_DIM  128
#define HID     64
#define HEADS   4
#define HC      256         // HEADS*HID
#define NEG_SLOPE 0.2f
#define N_SCAN_BLK 196      // ceil(50000/256)

// ---------------- scratch (device globals; no runtime alloc) ----------------
__device__ float    g_xl1[N_NODES * HC];
__device__ float    g_xr1[N_NODES * HC];
__device__ int      g_deg[N_NODES];
__device__ int      g_start[N_NODES];
__device__ int      g_cursor[N_NODES];
__device__ int      g_blksum[256];
__device__ int      g_blkoff[256];
__device__ float4   g_csr[N_E2];          // {src(bits), a0, a1, a2}
__device__ float    g_hl2[N_NODES];
__device__ float    g_hr2[N_NODES];
__device__ float    g_out2[N_NODES];
__device__ float    g_attr_sum[3];
__device__ unsigned g_smax;
__device__ float    g_ssum;

// ---------------- helpers ----------------
__device__ __forceinline__ unsigned encf(float f) {
    unsigned u = __float_as_uint(f);
    return (u & 0x80000000u) ? ~u : (u | 0x80000000u);
}
__device__ __forceinline__ float decf(unsigned u) {
    return (u & 0x80000000u) ? __uint_as_float(u & 0x7FFFFFFFu)
                             : __uint_as_float(~u);
}
__device__ __forceinline__ float warp_sum(float v) {
    #pragma unroll
    for (int o = 16; o; o >>= 1) v += __shfl_down_sync(0xffffffffu, v, o);
    return v;
}
__device__ __forceinline__ float f2tf32(float x) {
    uint32_t u;
    asm("cvt.rna.tf32.f32 %0, %1;" : "=r"(u) : "f"(x));
    return __uint_as_float(u);
}
__device__ __forceinline__ void mma_tf32(float c[4],
                                         uint32_t a0, uint32_t a1, uint32_t a2, uint32_t a3,
                                         uint32_t b0, uint32_t b1) {
    asm volatile("mma.sync.aligned.m16n8k8.row.col.f32.tf32.tf32.f32 "
                 "{%0,%1,%2,%3}, {%4,%5,%6,%7}, {%8,%9}, {%0,%1,%2,%3};"
                 : "+f"(c[0]), "+f"(c[1]), "+f"(c[2]), "+f"(c[3])
                 : "r"(a0), "r"(a1), "r"(a2), "r"(a3), "r"(b0), "r"(b1));
}
__device__ __forceinline__ float lrelu(float m) {
    return fmaxf(m, NEG_SLOPE * m);
}

// ---------------- init ----------------
__global__ void k_zero() {
    int tid = blockIdx.x * blockDim.x + threadIdx.x;
    int stride = gridDim.x * blockDim.x;
    for (int i = tid; i < N_NODES; i += stride) g_deg[i] = 0;
    if (tid == 0) {
        g_attr_sum[0] = 0.f; g_attr_sum[1] = 0.f; g_attr_sum[2] = 0.f;
        g_smax = 0u; g_ssum = 0.f;
    }
}

// mean of edge_attr columns (for self-loop fill)
__global__ void k_attr_mean(const float* __restrict__ ea) {
    float s0 = 0.f, s1 = 0.f, s2 = 0.f;
    for (int e = blockIdx.x * blockDim.x + threadIdx.x; e < N_EDGES;
         e += gridDim.x * blockDim.x) {
        s0 += ea[e * 3 + 0]; s1 += ea[e * 3 + 1]; s2 += ea[e * 3 + 2];
    }
    s0 = warp_sum(s0); s1 = warp_sum(s1); s2 = warp_sum(s2);
    if ((threadIdx.x & 31) == 0) {
        atomicAdd(&g_attr_sum[0], s0);
        atomicAdd(&g_attr_sum[1], s1);
        atomicAdd(&g_attr_sum[2], s2);
    }
}

// ---------------- CSR build ----------------
__global__ void k_count(const int* __restrict__ ei) {
    int e = blockIdx.x * blockDim.x + threadIdx.x;
    if (e >= N_E2) return;
    int dst = (e < N_EDGES) ? ei[N_EDGES + e] : e - N_EDGES;
    atomicAdd(&g_deg[dst], 1);
}

// parallel scan, stage 1
__global__ void k_scan1() {
    __shared__ int wTot[8];
    int tid = threadIdx.x, lane = tid & 31, wid = tid >> 5;
    int i = blockIdx.x * 256 + tid;
    int v = (i < N_NODES) ? g_deg[i] : 0;
    int x = v;
    #pragma unroll
    for (int o = 1; o < 32; o <<= 1) {
        int t = __shfl_up_sync(0xffffffffu, x, o);
        if (lane >= o) x += t;
    }
    if (lane == 31) wTot[wid] = x;
    __syncthreads();
    if (tid == 0) {
        int s = 0;
        #pragma unroll
        for (int j = 0; j < 8; j++) { int t = wTot[j]; wTot[j] = s; s += t; }
        g_blksum[blockIdx.x] = s;
    }
    __syncthreads();
    if (i < N_NODES) g_start[i] = x - v + wTot[wid];
}

// stage 2: scan of block sums
__global__ void k_scan2() {
    __shared__ int wTot[8];
    int tid = threadIdx.x, lane = tid & 31, wid = tid >> 5;
    int v = (tid < N_SCAN_BLK) ? g_blksum[tid] : 0;
    int x = v;
    #pragma unroll
    for (int o = 1; o < 32; o <<= 1) {
        int t = __shfl_up_sync(0xffffffffu, x, o);
        if (lane >= o) x += t;
    }
    if (lane == 31) wTot[wid] = x;
    __syncthreads();
    if (tid == 0) {
        int s = 0;
        #pragma unroll
        for (int j = 0; j < 8; j++) { int t = wTot[j]; wTot[j] = s; s += t; }
    }
    __syncthreads();
    g_blkoff[tid] = x - v + wTot[wid];
}

// stage 3: add block offsets
__global__ void k_scan3() {
    int i = blockIdx.x * blockDim.x + threadIdx.x;
    if (i >= N_NODES) return;
    int s = g_start[i] + g_blkoff[i >> 8];
    g_start[i] = s;
    g_cursor[i] = s;
}

// place packed entries {src, a0, a1, a2}
__global__ void k_place(const int* __restrict__ ei, const float* __restrict__ ea) {
    int e = blockIdx.x * blockDim.x + threadIdx.x;
    if (e >= N_E2) return;
    int src, dst; float a0, a1, a2;
    if (e < N_EDGES) {
        src = ei[e]; dst = ei[N_EDGES + e];
        a0 = ea[e * 3]; a1 = ea[e * 3 + 1]; a2 = ea[e * 3 + 2];
    } else {
        src = dst = e - N_EDGES;
        const float invE = 1.0f / N_EDGES;
        a0 = g_attr_sum[0] * invE; a1 = g_attr_sum[1] * invE; a2 = g_attr_sum[2] * invE;
    }
    int slot = atomicAdd(&g_cursor[dst], 1);
    g_csr[slot] = make_float4(__int_as_float(src), a0, a1, a2);
}

// ---------------- fused tf32 split-precision tensor-core GEMM ----------------
// bx<4: C=g_xl1, B=W1l ; bx>=4: C=g_xr1, B=W1r. Block tile 128m x 64n.
__global__ __launch_bounds__(256) void k_gemm(const float* __restrict__ A,
                                              const float* __restrict__ W1l,
                                              const float* __restrict__ W1r) {
    __shared__ float Ah[128][20], Al[128][20];
    __shared__ float Bh[16][72],  Bl[16][72];
    const int K = IN_DIM, M = HC;
    int bx = blockIdx.x;
    const float* B = (bx < 4) ? W1l : W1r;
    float* C = (bx < 4) ? g_xl1 : g_xr1;
    int row0 = blockIdx.y * 128, col0 = (bx & 3) * 64;
    int tid = threadIdx.x, lane = tid & 31, wid = tid >> 5;
    int wm = wid >> 1, wn = wid & 1;
    float acc[2][4][4] = {};

    for (int k0 = 0; k0 < K; k0 += 16) {
        #pragma unroll
        for (int i = tid; i < 512; i += 256) {
            int m = i >> 2, kq = (i & 3) * 4;
            int r = row0 + m;
            float4 v = (r < N_NODES)
                ? *reinterpret_cast<const float4*>(&A[(size_t)r * K + k0 + kq])
                : make_float4(0.f, 0.f, 0.f, 0.f);
            float h;
            h = f2tf32(v.x); Ah[m][kq + 0] = h; Al[m][kq + 0] = f2tf32(v.x - h);
            h = f2tf32(v.y); Ah[m][kq + 1] = h; Al[m][kq + 1] = f2tf32(v.y - h);
            h = f2tf32(v.z); Ah[m][kq + 2] = h; Al[m][kq + 2] = f2tf32(v.z - h);
            h = f2tf32(v.w); Ah[m][kq + 3] = h; Al[m][kq + 3] = f2tf32(v.w - h);
        }
        {
            int kk = tid >> 4, nq = (tid & 15) * 4;
            float4 v = *reinterpret_cast<const float4*>(&B[(size_t)(k0 + kk) * M + col0 + nq]);
            float h;
            h = f2tf32(v.x); Bh[kk][nq + 0] = h; Bl[kk][nq + 0] = f2tf32(v.x - h);
            h = f2tf32(v.y); Bh[kk][nq + 1] = h; Bl[kk][nq + 1] = f2tf32(v.y - h);
            h = f2tf32(v.z); Bh[kk][nq + 2] = h; Bl[kk][nq + 2] = f2tf32(v.z - h);
            h = f2tf32(v.w); Bh[kk][nq + 3] = h; Bl[kk][nq + 3] = f2tf32(v.w - h);
        }
        __syncthreads();
        #pragma unroll
        for (int ks = 0; ks < 16; ks += 8) {
            uint32_t ah[2][4], al[2][4], bh[4][2], bl[4][2];
            int kk = ks + (lane & 3);
            #pragma unroll
            for (int mt = 0; mt < 2; mt++) {
                int r0 = wm * 32 + mt * 16 + (lane >> 2);
                ah[mt][0] = __float_as_uint(Ah[r0][kk]);
                ah[mt][1] = __float_as_uint(Ah[r0 + 8][kk]);
                ah[mt][2] = __float_as_uint(Ah[r0][kk + 4]);
                ah[mt][3] = __float_as_uint(Ah[r0 + 8][kk + 4]);
                al[mt][0] = __float_as_uint(Al[r0][kk]);
                al[mt][1] = __float_as_uint(Al[r0 + 8][kk]);
                al[mt][2] = __float_as_uint(Al[r0][kk + 4]);
                al[mt][3] = __float_as_uint(Al[r0 + 8][kk + 4]);
            }
            #pragma unroll
            for (int nt = 0; nt < 4; nt++) {
                int cc = wn * 32 + nt * 8 + (lane >> 2);
                bh[nt][0] = __float_as_uint(Bh[kk][cc]);
                bh[nt][1] = __float_as_uint(Bh[kk + 4][cc]);
                bl[nt][0] = __float_as_uint(Bl[kk][cc]);
                bl[nt][1] = __float_as_uint(Bl[kk + 4][cc]);
            }
            #pragma unroll
            for (int mt = 0; mt < 2; mt++)
                #pragma unroll
                for (int nt = 0; nt < 4; nt++) {
                    mma_tf32(acc[mt][nt], ah[mt][0], ah[mt][1], ah[mt][2], ah[mt][3],
                             bh[nt][0], bh[nt][1]);
                    mma_tf32(acc[mt][nt], ah[mt][0], ah[mt][1], ah[mt][2], ah[mt][3],
                             bl[nt][0], bl[nt][1]);
                    mma_tf32(acc[mt][nt], al[mt][0], al[mt][1], al[mt][2], al[mt][3],
                             bh[nt][0], bh[nt][1]);
                }
        }
        __syncthreads();
    }
    #pragma unroll
    for (int mt = 0; mt < 2; mt++) {
        int row = row0 + wm * 32 + mt * 16 + (lane >> 2);
        #pragma unroll
        for (int nt = 0; nt < 4; nt++) {
            int col = col0 + wn * 32 + nt * 8 + 2 * (lane & 3);
            if (row < N_NODES)
                *reinterpret_cast<float2*>(&C[(size_t)row * M + col]) =
                    make_float2(acc[mt][nt][0], acc[mt][nt][1]);
            if (row + 8 < N_NODES)
                *reinterpret_cast<float2*>(&C[(size_t)(row + 8) * M + col]) =
                    make_float2(acc[mt][nt][2], acc[mt][nt][3]);
        }
    }
}

// ---------------- fused layer-1 GATv2 (all heads in one warp) ----------------
// lane l: head g = l>>3, sub j = l&7, channels cbase = g*64 + j*8 (8 scalars).
// Per-head logit reduction = 3-shfl butterfly within each 8-lane group.
// Epilogue fuses layer-2 node transform with full-warp reduction (no atomics).
__global__ __launch_bounds__(256) void k_gat1(const float* __restrict__ W1e,
                                              const float* __restrict__ att1,
                                              const float* __restrict__ b1,
                                              const float* __restrict__ W2l,
                                              const float* __restrict__ W2r) {
    int tid = threadIdx.x;
    int lane = tid & 31;
    int n = blockIdx.x * 8 + (tid >> 5);
    if (n >= N_NODES) return;
    int cbase = (lane >> 3) * 64 + (lane & 7) * 8;   // scalar channel base

    // per-lane weights for my 8 channels
    float4 w0a = *reinterpret_cast<const float4*>(&W1e[cbase]);
    float4 w0b = *reinterpret_cast<const float4*>(&W1e[cbase + 4]);
    float4 w1a = *reinterpret_cast<const float4*>(&W1e[256 + cbase]);
    float4 w1b = *reinterpret_cast<const float4*>(&W1e[256 + cbase + 4]);
    float4 w2a = *reinterpret_cast<const float4*>(&W1e[512 + cbase]);
    float4 w2b = *reinterpret_cast<const float4*>(&W1e[512 + cbase + 4]);
    float4 atA = *reinterpret_cast<const float4*>(&att1[cbase]);
    float4 atB = *reinterpret_cast<const float4*>(&att1[cbase + 4]);
    float4 r0  = *reinterpret_cast<const float4*>(&g_xr1[(size_t)n * HC + cbase]);
    float4 r1  = *reinterpret_cast<const float4*>(&g_xr1[(size_t)n * HC + cbase + 4]);

    int start = g_start[n];
    int end   = start + g_deg[n];
    float den = 0.f;
    float4 ax0 = make_float4(0.f, 0.f, 0.f, 0.f);
    float4 ax1 = make_float4(0.f, 0.f, 0.f, 0.f);
    for (int idx = start; idx < end; idx++) {
        float4 ent = g_csr[idx];
        int src = __float_as_int(ent.x);
        const float4* lp = reinterpret_cast<const float4*>(&g_xl1[(size_t)src * HC + cbase]);
        float4 l0 = lp[0], l1 = lp[1];
        float m, p;
        m = l0.x + r0.x + (ent.y * w0a.x + ent.z * w1a.x + ent.w * w2a.x);
        p  = lrelu(m) * atA.x;
        m = l0.y + r0.y + (ent.y * w0a.y + ent.z * w1a.y + ent.w * w2a.y);
        p += lrelu(m) * atA.y;
        m = l0.z + r0.z + (ent.y * w0a.z + ent.z * w1a.z + ent.w * w2a.z);
        p += lrelu(m) * atA.z;
        m = l0.w + r0.w + (ent.y * w0a.w + ent.z * w1a.w + ent.w * w2a.w);
        p += lrelu(m) * atA.w;
        m = l1.x + r1.x + (ent.y * w0b.x + ent.z * w1b.x + ent.w * w2b.x);
        p += lrelu(m) * atB.x;
        m = l1.y + r1.y + (ent.y * w0b.y + ent.z * w1b.y + ent.w * w2b.y);
        p += lrelu(m) * atB.y;
        m = l1.z + r1.z + (ent.y * w0b.z + ent.z * w1b.z + ent.w * w2b.z);
        p += lrelu(m) * atB.z;
        m = l1.w + r1.w + (ent.y * w0b.w + ent.z * w1b.w + ent.w * w2b.w);
        p += lrelu(m) * atB.w;
        // per-head sum: butterfly within the 8-lane group
        p += __shfl_xor_sync(0xffffffffu, p, 1);
        p += __shfl_xor_sync(0xffffffffu, p, 2);
        p += __shfl_xor_sync(0xffffffffu, p, 4);
        float ex = __expf(p);
        den += ex;
        ax0.x += ex * l0.x; ax0.y += ex * l0.y; ax0.z += ex * l0.z; ax0.w += ex * l0.w;
        ax1.x += ex * l1.x; ax1.y += ex * l1.y; ax1.z += ex * l1.z; ax1.w += ex * l1.w;
    }
    float inv = 1.0f / den;
    float4 bb0 = *reinterpret_cast<const float4*>(&b1[cbase]);
    float4 bb1 = *reinterpret_cast<const float4*>(&b1[cbase + 4]);
    float o[8];
    o[0] = ax0.x * inv + bb0.x; o[1] = ax0.y * inv + bb0.y;
    o[2] = ax0.z * inv + bb0.z; o[3] = ax0.w * inv + bb0.w;
    o[4] = ax1.x * inv + bb1.x; o[5] = ax1.y * inv + bb1.y;
    o[6] = ax1.z * inv + bb1.z; o[7] = ax1.w * inv + bb1.w;
    #pragma unroll
    for (int k = 0; k < 8; k++)
        o[k] = o[k] > 0.f ? o[k] : (__expf(o[k]) - 1.f);   // ELU
    float4 wl0 = *reinterpret_cast<const float4*>(&W2l[cbase]);
    float4 wl1 = *reinterpret_cast<const float4*>(&W2l[cbase + 4]);
    float4 wr0 = *reinterpret_cast<const float4*>(&W2r[cbase]);
    float4 wr1 = *reinterpret_cast<const float4*>(&W2r[cbase + 4]);
    float pl = o[0]*wl0.x + o[1]*wl0.y + o[2]*wl0.z + o[3]*wl0.w
             + o[4]*wl1.x + o[5]*wl1.y + o[6]*wl1.z + o[7]*wl1.w;
    float pr = o[0]*wr0.x + o[1]*wr0.y + o[2]*wr0.z + o[3]*wr0.w
             + o[4]*wr1.x + o[5]*wr1.y + o[6]*wr1.z + o[7]*wr1.w;
    pl = warp_sum(pl);
    pr = warp_sum(pr);
    if (lane == 0) { g_hl2[n] = pl; g_hr2[n] = pr; }
}

// ---------------- fused layer-2 GATv2 + scores ----------------
__global__ __launch_bounds__(256) void k_gat2(const float* __restrict__ W2e,
                                              const float* __restrict__ att2,
                                              const float* __restrict__ b2,
                                              float* __restrict__ out) {
    __shared__ float sW[3];
    __shared__ float sAtt, sB2;
    if (threadIdx.x < 3) sW[threadIdx.x] = W2e[threadIdx.x];
    if (threadIdx.x == 0) { sAtt = att2[0]; sB2 = b2[0]; }
    __syncthreads();

    int n = blockIdx.x * 8 + (threadIdx.x >> 5);
    int lane = threadIdx.x & 31;
    if (n >= N_NODES) return;
    float hr = g_hr2[n];
    int start = g_start[n];
    int end   = start + g_deg[n];
    float num = 0.f, den = 0.f;
    for (int idx = start + lane; idx < end; idx += 32) {
        float4 ent = g_csr[idx];
        int src = __float_as_int(ent.x);
        float hl = g_hl2[src];
        float m = hl + hr + ent.y * sW[0] + ent.z * sW[1] + ent.w * sW[2];
        float ex = __expf(sAtt * lrelu(m));
        den += ex;
        num += ex * hl;
    }
    num = warp_sum(num);
    den = warp_sum(den);
    if (lane == 0) {
        float s = num / den + sB2;
        g_out2[n] = s;
        out[N_NODES + n] = s;
    }
}

// ---------------- global softmax ----------------
__global__ void k_smax() {
    float m = -3.0e38f;
    for (int n = blockIdx.x * blockDim.x + threadIdx.x; n < N_NODES;
         n += gridDim.x * blockDim.x)
        m = fmaxf(m, g_out2[n]);
    #pragma unroll
    for (int o = 16; o; o >>= 1)
        m = fmaxf(m, __shfl_down_sync(0xffffffffu, m, o));
    if ((threadIdx.x & 31) == 0) atomicMax(&g_smax, encf(m));
}

__global__ void k_ssum() {
    float mx = decf(g_smax);
    float s = 0.f;
    for (int n = blockIdx.x * blockDim.x + threadIdx.x; n < N_NODES;
         n += gridDim.x * blockDim.x)
        s += __expf(g_out2[n] - mx);
    s = warp_sum(s);
    if ((threadIdx.x & 31) == 0) atomicAdd(&g_ssum, s);
}

__global__ void k_weights(float* __restrict__ out) {
    float mx = decf(g_smax);
    float inv = 1.0f / g_ssum;
    int n = blockIdx.x * blockDim.x + threadIdx.x;
    if (n >= N_NODES) return;
    out[n] = __expf(g_out2[n] - mx) * inv;
}

// ---------------- launch ----------------
extern "C" void kernel_launch(void* const* d_in, const int* in_sizes, int n_in,
                              void* d_out, int out_size) {
    const float* x    = (const float*)d_in[0];
    const float* ea   = (const float*)d_in[1];
    const float* W1l  = (const float*)d_in[2];
    const float* W1r  = (const float*)d_in[3];
    const float* W1e  = (const float*)d_in[4];
    const float* att1 = (const float*)d_in[5];
    const float* b1   = (const float*)d_in[6];
    const float* W2l  = (const float*)d_in[7];
    const float* W2r  = (const float*)d_in[8];
    const float* W2e  = (const float*)d_in[9];
    const float* att2 = (const float*)d_in[10];
    const float* b2   = (const float*)d_in[11];
    const int*   ei   = (const int*)d_in[12];
    float* out = (float*)d_out;

    int ethr_blocks = (N_E2 + 255) / 256;

    k_zero<<<256, 256>>>();                                 // 1
    k_attr_mean<<<256, 256>>>(ea);                          // 2
    k_count<<<ethr_blocks, 256>>>(ei);                      // 3
    dim3 gg(8, (N_NODES + 127) / 128);
    k_gemm<<<gg, 256>>>(x, W1l, W1r);                       // 4 (profiled slot)
    k_scan1<<<N_SCAN_BLK, 256>>>();                         // 5
    k_scan2<<<1, 256>>>();                                  // 6
    k_scan3<<<(N_NODES + 255) / 256, 256>>>();              // 7
    k_place<<<ethr_blocks, 256>>>(ei, ea);                  // 8
    k_gat1<<<(N_NODES + 7) / 8, 256>>>(W1e, att1, b1, W2l, W2r);  // 9
    k_gat2<<<(N_NODES + 7) / 8, 256>>>(W2e, att2, b2, out); // 10
    k_smax<<<128, 256>>>();                                 // 11
    k_ssum<<<128, 256>>>();                                 // 12
    k_weights<<<(N_NODES + 255) / 256, 256>>>(out);         // 13
}

// round 8
// speedup vs baseline: 1.3482x; 1.3482x over previous
#include <cuda_runtime.h>
#include <cstdint>

#define N_NODES 50000
#define N_EDGES 800000
#define N_E2    850000      // edges + self loops
#define IN_DIM  128
#define HID     64
#define HEADS   4
#define HC      256         // HEADS*HID
#define NEG_SLOPE 0.2f
#define N_SCAN_BLK 196      // ceil(50000/256)

// ---------------- scratch (device globals; no runtime alloc) ----------------
__device__ float    g_xl1[N_NODES * HC];
__device__ float    g_xr1[N_NODES * HC];
__device__ int      g_deg[N_NODES];
__device__ int      g_start[N_NODES];
__device__ int      g_cursor[N_NODES];
__device__ int      g_blksum[256];
__device__ int      g_blkoff[256];
__device__ float4   g_csr[N_E2];          // {src(bits), a0, a1, a2}
__device__ float    g_hl2[N_NODES];
__device__ float    g_hr2[N_NODES];
__device__ float    g_out2[N_NODES];
__device__ float    g_attr_sum[3];
__device__ unsigned g_smax;
__device__ float    g_ssum;

// ---------------- helpers ----------------
__device__ __forceinline__ unsigned encf(float f) {
    unsigned u = __float_as_uint(f);
    return (u & 0x80000000u) ? ~u : (u | 0x80000000u);
}
__device__ __forceinline__ float decf(unsigned u) {
    return (u & 0x80000000u) ? __uint_as_float(u & 0x7FFFFFFFu)
                             : __uint_as_float(~u);
}
__device__ __forceinline__ float warp_sum(float v) {
    #pragma unroll
    for (int o = 16; o; o >>= 1) v += __shfl_down_sync(0xffffffffu, v, o);
    return v;
}
__device__ __forceinline__ float warp_sum_all(float v) {
    #pragma unroll
    for (int o = 16; o; o >>= 1) v += __shfl_xor_sync(0xffffffffu, v, o);
    return v;
}
__device__ __forceinline__ float lrelu(float m) {
    return fmaxf(m, NEG_SLOPE * m);
}

// ---------------- init ----------------
__global__ void k_zero() {
    int tid = blockIdx.x * blockDim.x + threadIdx.x;
    int stride = gridDim.x * blockDim.x;
    for (int i = tid; i < N_NODES; i += stride) {
        g_deg[i] = 0; g_hl2[i] = 0.f; g_hr2[i] = 0.f;
    }
    if (tid == 0) {
        g_attr_sum[0] = 0.f; g_attr_sum[1] = 0.f; g_attr_sum[2] = 0.f;
        g_smax = 0u; g_ssum = 0.f;
    }
}

// mean of edge_attr columns (for self-loop fill)
__global__ void k_attr_mean(const float* __restrict__ ea) {
    float s0 = 0.f, s1 = 0.f, s2 = 0.f;
    for (int e = blockIdx.x * blockDim.x + threadIdx.x; e < N_EDGES;
         e += gridDim.x * blockDim.x) {
        s0 += ea[e * 3 + 0]; s1 += ea[e * 3 + 1]; s2 += ea[e * 3 + 2];
    }
    s0 = warp_sum(s0); s1 = warp_sum(s1); s2 = warp_sum(s2);
    if ((threadIdx.x & 31) == 0) {
        atomicAdd(&g_attr_sum[0], s0);
        atomicAdd(&g_attr_sum[1], s1);
        atomicAdd(&g_attr_sum[2], s2);
    }
}

// ---------------- CSR build ----------------
__global__ void k_count(const int* __restrict__ ei) {
    int e = blockIdx.x * blockDim.x + threadIdx.x;
    if (e >= N_E2) return;
    int dst = (e < N_EDGES) ? ei[N_EDGES + e] : e - N_EDGES;
    atomicAdd(&g_deg[dst], 1);
}

// ---------------- SGEMM (SIMT, proven): C[N,256] = A[N,128] @ B[128,256] ----
// bx<4: C=g_xl1, B=W1l ; bx>=4: C=g_xr1, B=W1r. BM=128 BN=64 BK=16, 8x4/thr.
__global__ __launch_bounds__(256) void k_gemm(const float* __restrict__ A,
                                              const float* __restrict__ W1l,
                                              const float* __restrict__ W1r) {
    __shared__ float As[16][132];
    __shared__ float Bs[16][64];
    const int K = IN_DIM, M = HC;
    int bx = blockIdx.x;
    const float* B = (bx < 4) ? W1l : W1r;
    float* C = (bx < 4) ? g_xl1 : g_xr1;
    int row0 = blockIdx.y * 128, col0 = (bx & 3) * 64;
    int tid = threadIdx.x;
    int tr = tid >> 4, tc = tid & 15;
    float acc[8][4] = {};
    for (int k0 = 0; k0 < K; k0 += 16) {
        #pragma unroll
        for (int i = tid; i < 512; i += 256) {
            int m = i >> 2, kq = (i & 3) * 4;
            int r = row0 + m;
            float4 v = (r < N_NODES)
                ? *reinterpret_cast<const float4*>(&A[(size_t)r * K + k0 + kq])
                : make_float4(0.f, 0.f, 0.f, 0.f);
            As[kq + 0][m] = v.x; As[kq + 1][m] = v.y;
            As[kq + 2][m] = v.z; As[kq + 3][m] = v.w;
        }
        {
            int kk = tid >> 4, nq = (tid & 15) * 4;
            *reinterpret_cast<float4*>(&Bs[kk][nq]) =
                *reinterpret_cast<const float4*>(&B[(size_t)(k0 + kk) * M + col0 + nq]);
        }
        __syncthreads();
        #pragma unroll
        for (int kk = 0; kk < 16; kk++) {
            float4 a0 = *reinterpret_cast<const float4*>(&As[kk][tr * 8]);
            float4 a1 = *reinterpret_cast<const float4*>(&As[kk][tr * 8 + 4]);
            float4 b4 = *reinterpret_cast<const float4*>(&Bs[kk][tc * 4]);
            float a[8] = {a0.x, a0.y, a0.z, a0.w, a1.x, a1.y, a1.z, a1.w};
            float b[4] = {b4.x, b4.y, b4.z, b4.w};
            #pragma unroll
            for (int u = 0; u < 8; u++)
                #pragma unroll
                for (int v = 0; v < 4; v++)
                    acc[u][v] += a[u] * b[v];
        }
        __syncthreads();
    }
    #pragma unroll
    for (int u = 0; u < 8; u++) {
        int r = row0 + tr * 8 + u;
        if (r < N_NODES)
            *reinterpret_cast<float4*>(&C[(size_t)r * M + col0 + tc * 4]) =
                make_float4(acc[u][0], acc[u][1], acc[u][2], acc[u][3]);
    }
}

// parallel scan, stage 1
__global__ void k_scan1() {
    __shared__ int wTot[8];
    int tid = threadIdx.x, lane = tid & 31, wid = tid >> 5;
    int i = blockIdx.x * 256 + tid;
    int v = (i < N_NODES) ? g_deg[i] : 0;
    int x = v;
    #pragma unroll
    for (int o = 1; o < 32; o <<= 1) {
        int t = __shfl_up_sync(0xffffffffu, x, o);
        if (lane >= o) x += t;
    }
    if (lane == 31) wTot[wid] = x;
    __syncthreads();
    if (tid == 0) {
        int s = 0;
        #pragma unroll
        for (int j = 0; j < 8; j++) { int t = wTot[j]; wTot[j] = s; s += t; }
        g_blksum[blockIdx.x] = s;
    }
    __syncthreads();
    if (i < N_NODES) g_start[i] = x - v + wTot[wid];
}

// stage 2: scan of block sums
__global__ void k_scan2() {
    __shared__ int wTot[8];
    int tid = threadIdx.x, lane = tid & 31, wid = tid >> 5;
    int v = (tid < N_SCAN_BLK) ? g_blksum[tid] : 0;
    int x = v;
    #pragma unroll
    for (int o = 1; o < 32; o <<= 1) {
        int t = __shfl_up_sync(0xffffffffu, x, o);
        if (lane >= o) x += t;
    }
    if (lane == 31) wTot[wid] = x;
    __syncthreads();
    if (tid == 0) {
        int s = 0;
        #pragma unroll
        for (int j = 0; j < 8; j++) { int t = wTot[j]; wTot[j] = s; s += t; }
    }
    __syncthreads();
    g_blkoff[tid] = x - v + wTot[wid];
}

// stage 3: add block offsets
__global__ void k_scan3() {
    int i = blockIdx.x * blockDim.x + threadIdx.x;
    if (i >= N_NODES) return;
    int s = g_start[i] + g_blkoff[i >> 8];
    g_start[i] = s;
    g_cursor[i] = s;
}

// place packed entries {src, a0, a1, a2}
__global__ void k_place(const int* __restrict__ ei, const float* __restrict__ ea) {
    int e = blockIdx.x * blockDim.x + threadIdx.x;
    if (e >= N_E2) return;
    int src, dst; float a0, a1, a2;
    if (e < N_EDGES) {
        src = ei[e]; dst = ei[N_EDGES + e];
        a0 = ea[e * 3]; a1 = ea[e * 3 + 1]; a2 = ea[e * 3 + 2];
    } else {
        src = dst = e - N_EDGES;
        const float invE = 1.0f / N_EDGES;
        a0 = g_attr_sum[0] * invE; a1 = g_attr_sum[1] * invE; a2 = g_attr_sum[2] * invE;
    }
    int slot = atomicAdd(&g_cursor[dst], 1);
    g_csr[slot] = make_float4(__int_as_float(src), a0, a1, a2);
}

// ---------------- fused layer-1 GATv2 + layer-2 node transform ---------------
// one warp per (dst node, head) — 200k warps. Packed CSR: 1 LDG.128 broadcast
// per edge for {src, attrs} + 256B coalesced xl gather.
__global__ __launch_bounds__(256) void k_gat1(const float* __restrict__ W1e,
                                              const float* __restrict__ att1,
                                              const float* __restrict__ b1,
                                              const float* __restrict__ W2l,
                                              const float* __restrict__ W2r) {
    __shared__ float sW[768];     // W1e (3 x 256)
    __shared__ float sA[256];     // att1
    int tid = threadIdx.x;
    for (int i = tid; i < 768; i += 256) sW[i] = W1e[i];
    if (tid < 256) sA[tid] = att1[tid];
    __syncthreads();

    int gw = blockIdx.x * 8 + (tid >> 5);
    int lane = tid & 31;
    int n = gw >> 2;
    int h = gw & 3;
    if (n >= N_NODES) return;

    int c2 = h * 32 + lane;
    int i = c2 * 2;
    const float w0 = sW[i],     w1 = sW[256 + i],     w2 = sW[512 + i];
    const float w0b = sW[i + 1], w1b = sW[256 + i + 1], w2b = sW[512 + i + 1];
    const float attA = sA[i], attB = sA[i + 1];
    float2 r = reinterpret_cast<const float2*>(g_xr1)[(size_t)n * 128 + c2];

    int start = g_start[n];
    int end   = start + g_deg[n];
    float den = 0.f, ax = 0.f, ay = 0.f;
    for (int idx = start; idx < end; idx++) {
        float4 ent = g_csr[idx];                       // broadcast (same addr all lanes)
        int src = __float_as_int(ent.x);
        float2 l = reinterpret_cast<const float2*>(g_xl1)[(size_t)src * 128 + c2];
        float e0 = ent.y * w0  + ent.z * w1  + ent.w * w2;
        float e1 = ent.y * w0b + ent.z * w1b + ent.w * w2b;
        float m0 = lrelu(l.x + r.x + e0);
        float m1 = lrelu(l.y + r.y + e1);
        float p = warp_sum_all(m0 * attA + m1 * attB);
        float ex = __expf(p);
        den += ex;
        ax += ex * l.x;
        ay += ex * l.y;
    }
    float inv = 1.0f / den;
    float o0 = ax * inv + b1[i];
    float o1 = ay * inv + b1[i + 1];
    o0 = o0 > 0.f ? o0 : (__expf(o0) - 1.f);           // ELU
    o1 = o1 > 0.f ? o1 : (__expf(o1) - 1.f);
    float pl = o0 * W2l[i] + o1 * W2l[i + 1];
    float pr = o0 * W2r[i] + o1 * W2r[i + 1];
    pl = warp_sum(pl);
    pr = warp_sum(pr);
    if (lane == 0) {
        atomicAdd(&g_hl2[n], pl);
        atomicAdd(&g_hr2[n], pr);
    }
}

// ---------------- fused layer-2 GATv2 + scores ----------------
__global__ __launch_bounds__(256) void k_gat2(const float* __restrict__ W2e,
                                              const float* __restrict__ att2,
                                              const float* __restrict__ b2,
                                              float* __restrict__ out) {
    __shared__ float sW[3];
    __shared__ float sAtt, sB2;
    if (threadIdx.x < 3) sW[threadIdx.x] = W2e[threadIdx.x];
    if (threadIdx.x == 0) { sAtt = att2[0]; sB2 = b2[0]; }
    __syncthreads();

    int n = blockIdx.x * 8 + (threadIdx.x >> 5);
    int lane = threadIdx.x & 31;
    if (n >= N_NODES) return;
    float hr = g_hr2[n];
    int start = g_start[n];
    int end   = start + g_deg[n];
    float num = 0.f, den = 0.f;
    for (int idx = start + lane; idx < end; idx += 32) {
        float4 ent = g_csr[idx];
        int src = __float_as_int(ent.x);
        float hl = g_hl2[src];
        float m = hl + hr + ent.y * sW[0] + ent.z * sW[1] + ent.w * sW[2];
        float ex = __expf(sAtt * lrelu(m));
        den += ex;
        num += ex * hl;
    }
    num = warp_sum(num);
    den = warp_sum(den);
    if (lane == 0) {
        float s = num / den + sB2;
        g_out2[n] = s;
        out[N_NODES + n] = s;
    }
}

// ---------------- global softmax ----------------
__global__ void k_smax() {
    float m = -3.0e38f;
    for (int n = blockIdx.x * blockDim.x + threadIdx.x; n < N_NODES;
         n += gridDim.x * blockDim.x)
        m = fmaxf(m, g_out2[n]);
    #pragma unroll
    for (int o = 16; o; o >>= 1)
        m = fmaxf(m, __shfl_down_sync(0xffffffffu, m, o));
    if ((threadIdx.x & 31) == 0) atomicMax(&g_smax, encf(m));
}

__global__ void k_ssum() {
    float mx = decf(g_smax);
    float s = 0.f;
    for (int n = blockIdx.x * blockDim.x + threadIdx.x; n < N_NODES;
         n += gridDim.x * blockDim.x)
        s += __expf(g_out2[n] - mx);
    s = warp_sum(s);
    if ((threadIdx.x & 31) == 0) atomicAdd(&g_ssum, s);
}

__global__ void k_weights(float* __restrict__ out) {
    float mx = decf(g_smax);
    float inv = 1.0f / g_ssum;
    int n = blockIdx.x * blockDim.x + threadIdx.x;
    if (n >= N_NODES) return;
    out[n] = __expf(g_out2[n] - mx) * inv;
}

// ---------------- launch ----------------
extern "C" void kernel_launch(void* const* d_in, const int* in_sizes, int n_in,
                              void* d_out, int out_size) {
    const float* x    = (const float*)d_in[0];
    const float* ea   = (const float*)d_in[1];
    const float* W1l  = (const float*)d_in[2];
    const float* W1r  = (const float*)d_in[3];
    const float* W1e  = (const float*)d_in[4];
    const float* att1 = (const float*)d_in[5];
    const float* b1   = (const float*)d_in[6];
    const float* W2l  = (const float*)d_in[7];
    const float* W2r  = (const float*)d_in[8];
    const float* W2e  = (const float*)d_in[9];
    const float* att2 = (const float*)d_in[10];
    const float* b2   = (const float*)d_in[11];
    const int*   ei   = (const int*)d_in[12];
    float* out = (float*)d_out;

    int ethr_blocks = (N_E2 + 255) / 256;

    k_zero<<<256, 256>>>();                                 // 1
    k_attr_mean<<<256, 256>>>(ea);                          // 2
    k_count<<<ethr_blocks, 256>>>(ei);                      // 3
    dim3 gg(8, (N_NODES + 127) / 128);
    k_gemm<<<gg, 256>>>(x, W1l, W1r);                       // 4 (profiled slot)
    k_scan1<<<N_SCAN_BLK, 256>>>();                         // 5
    k_scan2<<<1, 256>>>();                                  // 6
    k_scan3<<<(N_NODES + 255) / 256, 256>>>();              // 7
    k_place<<<ethr_blocks, 256>>>(ei, ea);                  // 8
    k_gat1<<<(N_NODES * HEADS + 7) / 8, 256>>>(W1e, att1, b1, W2l, W2r);  // 9
    k_gat2<<<(N_NODES + 7) / 8, 256>>>(W2e, att2, b2, out); // 10
    k_smax<<<128, 256>>>();                                 // 11
    k_ssum<<<128, 256>>>();                                 // 12
    k_weights<<<(N_NODES + 255) / 256, 256>>>(out);         // 13
}